// round 3
// baseline (speedup 1.0000x reference)
#include <cuda_runtime.h>
#include <cuda_fp16.h>
#include <cstdint>

#define THREADS     512
#define B_ROWS      256
#define D_K         2048
#define N_FEAT      65536
#define N_TILE      128
#define KC          64
#define NSTAGE      (D_K / KC)            // 32
#define A_BYTES     (B_ROWS * KC * 2)     // 32768
#define B_BYTES     (N_TILE * KC * 2)     // 16384
#define STAGE_BYTES (A_BYTES + B_BYTES)   // 49152
#define SMEM_DYN    (1024 + 2 * STAGE_BYTES)

// 1MB fp16 copy of `inputs` (pre-converted once per launch, L2-resident)
__device__ __half g_a16[B_ROWS * D_K];

static __device__ __forceinline__ uint32_t smem_u32(const void* p) {
    uint32_t a;
    asm("{ .reg .u64 t; cvta.to.shared.u64 t, %1; cvt.u32.u64 %0, t; }"
        : "=r"(a) : "l"(p));
    return a;
}

#define CP_ASYNC16(dst, src) \
    asm volatile("cp.async.cg.shared.global [%0], [%1], 16;" \
                 :: "r"(dst), "l"(src) : "memory")
#define CP_COMMIT() asm volatile("cp.async.commit_group;" ::: "memory")
#define CP_WAIT0()  asm volatile("cp.async.wait_group 0;"  ::: "memory")

#define LDSM_X4(r, addr) \
    asm volatile("ldmatrix.sync.aligned.m8n8.x4.shared.b16 {%0,%1,%2,%3}, [%4];" \
        : "=r"((r)[0]), "=r"((r)[1]), "=r"((r)[2]), "=r"((r)[3]) : "r"(addr))

#define MMA16816(c, a, b0, b1) \
    asm volatile("mma.sync.aligned.m16n8k16.row.col.f32.f16.f16.f32 " \
        "{%0,%1,%2,%3}, {%4,%5,%6,%7}, {%8,%9}, {%0,%1,%2,%3};" \
        : "+f"((c)[0]), "+f"((c)[1]), "+f"((c)[2]), "+f"((c)[3]) \
        : "r"((a)[0]), "r"((a)[1]), "r"((a)[2]), "r"((a)[3]), "r"(b0), "r"(b1))

#define STS64(addr, v0, v1) \
    asm volatile("st.shared.v2.b32 [%0], {%1,%2};" \
                 :: "r"(addr), "r"(v0), "r"(v1) : "memory")

// ---------------- pre-kernel: inputs fp32 -> fp16 scratch ----------------
__global__ void cvt_a_kernel(const float* __restrict__ inputs) {
    int i = blockIdx.x * blockDim.x + threadIdx.x;
    if (i < (B_ROWS * D_K) / 2) {
        float2 v = reinterpret_cast<const float2*>(inputs)[i];
        reinterpret_cast<__half2*>(g_a16)[i] = __floats2half2_rn(v.x, v.y);
    }
}

// ---------------- main GEMM kernel (HMMA mma.sync path) ----------------
__global__ __launch_bounds__(THREADS, 1)
void gemm_hmma_kernel(const float* __restrict__ feats, float* __restrict__ out) {
    extern __shared__ char dsm[];
    const uint32_t raw = smem_u32(dsm);
    const uint32_t SB = (raw + 1023u) & ~1023u;   // 1KB-aligned base

    const int tid = threadIdx.x;
    const int wid = tid >> 5;
    const int lid = tid & 31;
    const int wm  = wid & 3;    // warp M index (4): 64 rows each
    const int wn  = wid >> 2;   // warp N index (4): 32 cols each
    const int n0  = blockIdx.x * N_TILE;

    // ldmatrix addressing, swizzle-correct per k-step:
    // SW128 mask = (row & 7) << 4, applied to the 16B-chunk index.
    // A: lanes 0-15 -> rows (lid&15) @ kchunk 0; lanes 16-31 same rows @ kchunk 1
    const uint32_t a_row    = (uint32_t)(wm * 64 + (lid & 15));
    const uint32_t a_rowoff = a_row << 7;
    const uint32_t a_sw     = a_row & 7;
    const uint32_t a_kc     = (uint32_t)(lid >> 4);         // 0 or 1
    // B: lanes 0-7: rows n0..7 kc0 | 8-15: same rows kc1 | 16-23: rows +8 kc0 | 24-31: +8 kc1
    const uint32_t b_row    = (uint32_t)(wn * 32 + ((lid >> 4) << 3) + (lid & 7));
    const uint32_t b_rowoff = b_row << 7;
    const uint32_t b_sw     = b_row & 7;
    const uint32_t b_kc     = (uint32_t)((lid >> 3) & 1);   // 0 or 1

    float acc[4][4][4];
    #pragma unroll
    for (int mf = 0; mf < 4; ++mf)
        #pragma unroll
        for (int nf = 0; nf < 4; ++nf)
            #pragma unroll
            for (int k = 0; k < 4; ++k)
                acc[mf][nf][k] = 0.0f;

    // B staging: 16 raw fp32 per thread (converted at STS time next iter)
    float fst[16];

    // per-thread staging coordinates
    const int brow = tid >> 4;          // 0..31   (+i*32)
    const int bc4  = tid & 15;          // float4 index within 64-float row
    const int arow = tid >> 3;          // 0..63   (+i*64)
    const int ac   = tid & 7;           // 16B chunk within 128B row

    // swizzled SMEM dst offsets (constant across stages; full offsets -> correct)
    uint32_t bsts_off[4], acp_off[4];
    #pragma unroll
    for (int i = 0; i < 4; ++i) {
        uint32_t ob = ((uint32_t)(brow + i * 32) << 7) | ((uint32_t)bc4 << 3);
        bsts_off[i] = ob ^ ((ob >> 3) & 0x70);
        uint32_t oa = ((uint32_t)(arow + i * 64) << 7) | ((uint32_t)ac << 4);
        acp_off[i] = oa ^ ((oa >> 3) & 0x70);
    }

    // ---- prologue: stage 0 loads ----
    #pragma unroll
    for (int i = 0; i < 4; ++i) {
        const float4 v = *reinterpret_cast<const float4*>(
            feats + (size_t)(n0 + brow + i * 32) * D_K + bc4 * 4);
        fst[i*4+0] = v.x; fst[i*4+1] = v.y; fst[i*4+2] = v.z; fst[i*4+3] = v.w;
    }
    #pragma unroll
    for (int i = 0; i < 4; ++i) {
        const __half* src = g_a16 + (size_t)(arow + i * 64) * D_K + ac * 8;
        CP_ASYNC16(SB + acp_off[i], src);
    }
    CP_COMMIT();

    for (int s = 0; s < NSTAGE; ++s) {
        const int buf = s & 1;
        const uint32_t Ab = SB + buf * STAGE_BYTES;
        const uint32_t Bb = Ab + A_BYTES;

        // STS B(s): convert staged fp32 -> fp16, swizzled 8B stores
        #pragma unroll
        for (int i = 0; i < 4; ++i) {
            __half2 h0 = __floats2half2_rn(fst[i*4+0], fst[i*4+1]);
            __half2 h1 = __floats2half2_rn(fst[i*4+2], fst[i*4+3]);
            STS64(Bb + bsts_off[i],
                  *reinterpret_cast<uint32_t*>(&h0),
                  *reinterpret_cast<uint32_t*>(&h1));
        }
        CP_WAIT0();          // A(s) landed
        __syncthreads();

        // issue stage s+1 loads (overlap with compute below)
        if (s + 1 < NSTAGE) {
            const int kc1 = (s + 1) * KC;
            #pragma unroll
            for (int i = 0; i < 4; ++i) {
                const float4 v = *reinterpret_cast<const float4*>(
                    feats + (size_t)(n0 + brow + i * 32) * D_K + kc1 + bc4 * 4);
                fst[i*4+0] = v.x; fst[i*4+1] = v.y; fst[i*4+2] = v.z; fst[i*4+3] = v.w;
            }
            const uint32_t An = SB + (buf ^ 1) * STAGE_BYTES;
            #pragma unroll
            for (int i = 0; i < 4; ++i) {
                const __half* src = g_a16 + (size_t)(arow + i * 64) * D_K + kc1 + ac * 8;
                CP_ASYNC16(An + acp_off[i], src);
            }
            CP_COMMIT();
        }

        // ---- compute stage s: 4 k-steps of 16 ----
        #pragma unroll
        for (int ks = 0; ks < 4; ++ks) {
            uint32_t ar[4][4], br[2][4];
            #pragma unroll
            for (int mf = 0; mf < 4; ++mf)
                LDSM_X4(ar[mf], Ab + a_rowoff + (uint32_t)(mf * 2048)
                                 + (((a_kc + ks * 2) ^ a_sw) << 4));
            #pragma unroll
            for (int nh = 0; nh < 2; ++nh)
                LDSM_X4(br[nh], Bb + b_rowoff + (uint32_t)(nh * 2048)
                                 + (((b_kc + ks * 2) ^ b_sw) << 4));
            #pragma unroll
            for (int mf = 0; mf < 4; ++mf)
                #pragma unroll
                for (int nf = 0; nf < 4; ++nf)
                    MMA16816(acc[mf][nf], ar[mf],
                             br[nf >> 1][(nf & 1) * 2],
                             br[nf >> 1][(nf & 1) * 2 + 1]);
        }
    }

    // ---- epilogue: direct STG.64, 32B-sector aligned ----
    const int mrow = wm * 64 + (lid >> 2);
    const int ncol = n0 + wn * 32 + 2 * (lid & 3);
    #pragma unroll
    for (int mf = 0; mf < 4; ++mf) {
        float* r0 = out + (size_t)(mrow + mf * 16) * N_FEAT;
        float* r1 = r0 + (size_t)8 * N_FEAT;
        #pragma unroll
        for (int nf = 0; nf < 4; ++nf) {
            const int c = ncol + nf * 8;
            *reinterpret_cast<float2*>(r0 + c) =
                make_float2(acc[mf][nf][0], acc[mf][nf][1]);
            *reinterpret_cast<float2*>(r1 + c) =
                make_float2(acc[mf][nf][2], acc[mf][nf][3]);
        }
    }
}

// ---------------- launch ----------------
extern "C" void kernel_launch(void* const* d_in, const int* in_sizes, int n_in,
                              void* d_out, int out_size) {
    const float* inputs = (const float*)d_in[0];   // [256, 2048] fp32
    const float* feats  = (const float*)d_in[3];   // [65536, 2048] fp32
    float* out = (float*)d_out;                    // [256, 65536] fp32

    cudaFuncSetAttribute(gemm_hmma_kernel,
                         cudaFuncAttributeMaxDynamicSharedMemorySize, SMEM_DYN);

    cvt_a_kernel<<<(B_ROWS * D_K / 2 + 255) / 256, 256>>>(inputs);
    gemm_hmma_kernel<<<N_FEAT / N_TILE, THREADS, SMEM_DYN>>>(feats, out);
}